// round 4
// baseline (speedup 1.0000x reference)
#include <cuda_runtime.h>
#include <cstdint>

#define Bn 4
#define Sn 4096
#define Hn 2048
#define EPSf 1e-6f

#define RS 16                // s-rows per block
#define CH 4                 // rows per chunk
#define NCHUNK (RS / CH)     // 4
#define NBUF 3               // triple buffer
#define H4 (Hn / 4)          // 512 float4 per row
#define CHUNK_F4 (CH * H4)   // 2048 float4 = 32 KB per chunk

#define SMEM_BYTES (NBUF * CHUNK_F4 * 16 + 64)

__device__ __forceinline__ void cp_async16(uint32_t saddr, const void* g) {
    asm volatile("cp.async.cg.shared.global [%0], [%1], 16;\n" :: "r"(saddr), "l"(g));
}
__device__ __forceinline__ void cp_commit() {
    asm volatile("cp.async.commit_group;\n" ::: "memory");
}
template <int N> __device__ __forceinline__ void cp_wait() {
    asm volatile("cp.async.wait_group %0;\n" :: "n"(N) : "memory");
}

// ---------------------------------------------------------------------------
// Fused RMSNorm + depthwise causal conv1d (K=4) + bias.
// Single DRAM read of x via cp.async triple-buffered smem staging; rowsq and
// conv both read smem; streaming stores for the output.
// grid = (S/RS, B), block = 512, dyn smem = 96 KB (2 blocks/SM).
// ---------------------------------------------------------------------------
__global__ __launch_bounds__(512, 2) void fused_kernel(const float* __restrict__ x,
                                                       const float* __restrict__ nw,
                                                       const float* __restrict__ cw,
                                                       const float* __restrict__ cb,
                                                       float*       __restrict__ out) {
    extern __shared__ float4 smem[];
    float4* buf  = smem;                                   // [NBUF][CHUNK_F4]
    float*  s_ir = reinterpret_cast<float*>(smem + NBUF * CHUNK_F4);  // [CH]
    float*  s_hir = s_ir + CH;                             // [3] halo inv_rms

    const int b    = blockIdx.y;
    const int s0   = blockIdx.x * RS;
    const int tid  = threadIdx.x;
    const int warp = tid >> 5;
    const int lane = tid & 31;

    const float* xb = x   + (size_t)b * Sn * Hn;
    float*       ob = out + (size_t)b * Sn * Hn;

    // ---- issue helper: stage chunk c (rows s0+c*CH .. +CH-1, contiguous) ----
    auto issue = [&](int c) {
        const float4* src = reinterpret_cast<const float4*>(xb + (size_t)(s0 + c * CH) * Hn);
        float4* dst = buf + (c % NBUF) * CHUNK_F4;
#pragma unroll
        for (int i = 0; i < 4; i++) {
            int idx = tid + 512 * i;
            cp_async16((uint32_t)__cvta_generic_to_shared(dst + idx), src + idx);
        }
        cp_commit();
    };

    // ---- prologue: fill the pipeline ----
    issue(0);
    issue(1);
    issue(2);

    // Halo inv_rms: warps 0..2 reduce rows s0-3..s0-1 straight from GMEM.
    if (warp < 3) {
        const int s = s0 - 3 + warp;
        float a0 = 0.f, a1 = 0.f, a2 = 0.f, a3 = 0.f;
        if (s >= 0) {
            const float4* xr = reinterpret_cast<const float4*>(xb + (size_t)s * Hn);
#pragma unroll
            for (int i = 0; i < 16; i += 4) {
                float4 v0 = __ldg(&xr[lane + 32 * (i + 0)]);
                float4 v1 = __ldg(&xr[lane + 32 * (i + 1)]);
                float4 v2 = __ldg(&xr[lane + 32 * (i + 2)]);
                float4 v3 = __ldg(&xr[lane + 32 * (i + 3)]);
                a0 = fmaf(v0.x, v0.x, fmaf(v0.y, v0.y, fmaf(v0.z, v0.z, fmaf(v0.w, v0.w, a0))));
                a1 = fmaf(v1.x, v1.x, fmaf(v1.y, v1.y, fmaf(v1.z, v1.z, fmaf(v1.w, v1.w, a1))));
                a2 = fmaf(v2.x, v2.x, fmaf(v2.y, v2.y, fmaf(v2.z, v2.z, fmaf(v2.w, v2.w, a2))));
                a3 = fmaf(v3.x, v3.x, fmaf(v3.y, v3.y, fmaf(v3.z, v3.z, fmaf(v3.w, v3.w, a3))));
            }
        }
        float ss = (a0 + a1) + (a2 + a3);
#pragma unroll
        for (int o = 16; o; o >>= 1)
            ss += __shfl_xor_sync(0xFFFFFFFFu, ss, o);
        if (lane == 0)
            s_hir[warp] = (s >= 0) ? rsqrtf(ss * (1.0f / (float)Hn) + EPSf) : 0.0f;
    }
    __syncthreads();

    // ---- per-thread constants: taps (norm_weight folded), bias ----
    const int h4 = tid;
    const int h  = h4 * 4;
    const float4* cw4 = reinterpret_cast<const float4*>(cw);
    const float4 nwv = __ldg(&reinterpret_cast<const float4*>(nw)[h4]);
    float4 t0 = __ldg(&cw4[h + 0]);
    float4 t1 = __ldg(&cw4[h + 1]);
    float4 t2 = __ldg(&cw4[h + 2]);
    float4 t3 = __ldg(&cw4[h + 3]);
    t0.x *= nwv.x; t0.y *= nwv.x; t0.z *= nwv.x; t0.w *= nwv.x;
    t1.x *= nwv.y; t1.y *= nwv.y; t1.z *= nwv.y; t1.w *= nwv.y;
    t2.x *= nwv.z; t2.y *= nwv.z; t2.z *= nwv.z; t2.w *= nwv.z;
    t3.x *= nwv.w; t3.y *= nwv.w; t3.z *= nwv.w; t3.w *= nwv.w;
    const float4 bias = __ldg(&reinterpret_cast<const float4*>(cb)[h4]);

    // ---- rolling window from halo rows (GMEM re-read: L1/L2 hit, tiny) ----
    float4 xm3, xm2, xm1;
    {
        float4 pre[3];
#pragma unroll
        for (int j = 0; j < 3; j++) {
            const int s = s0 - 3 + j;
            if (s >= 0) {
                float4 v = __ldg(&reinterpret_cast<const float4*>(xb + (size_t)s * Hn)[h4]);
                const float r = s_hir[j];
                pre[j].x = v.x * r; pre[j].y = v.y * r; pre[j].z = v.z * r; pre[j].w = v.w * r;
            } else {
                pre[j] = make_float4(0.f, 0.f, 0.f, 0.f);
            }
        }
        xm3 = pre[0]; xm2 = pre[1]; xm1 = pre[2];
    }

    // ---- pipeline over chunks ----
#pragma unroll
    for (int c = 0; c < NCHUNK; c++) {
        // wait for chunk c (allow later chunks to stay in flight)
        if (c <= 1)      cp_wait<2>();
        else if (c == 2) cp_wait<1>();
        else             cp_wait<0>();
        __syncthreads();

        const float4* bufc = buf + (c % NBUF) * CHUNK_F4;

        // rowsq: warp w reduces row w of the chunk from smem
        if (warp < CH) {
            const float4* row = bufc + warp * H4;
            float a0 = 0.f, a1 = 0.f, a2 = 0.f, a3 = 0.f;
#pragma unroll
            for (int i = 0; i < 16; i += 4) {
                float4 v0 = row[lane + 32 * (i + 0)];
                float4 v1 = row[lane + 32 * (i + 1)];
                float4 v2 = row[lane + 32 * (i + 2)];
                float4 v3 = row[lane + 32 * (i + 3)];
                a0 = fmaf(v0.x, v0.x, fmaf(v0.y, v0.y, fmaf(v0.z, v0.z, fmaf(v0.w, v0.w, a0))));
                a1 = fmaf(v1.x, v1.x, fmaf(v1.y, v1.y, fmaf(v1.z, v1.z, fmaf(v1.w, v1.w, a1))));
                a2 = fmaf(v2.x, v2.x, fmaf(v2.y, v2.y, fmaf(v2.z, v2.z, fmaf(v2.w, v2.w, a2))));
                a3 = fmaf(v3.x, v3.x, fmaf(v3.y, v3.y, fmaf(v3.z, v3.z, fmaf(v3.w, v3.w, a3))));
            }
            float ss = (a0 + a1) + (a2 + a3);
#pragma unroll
            for (int o = 16; o; o >>= 1)
                ss += __shfl_xor_sync(0xFFFFFFFFu, ss, o);
            if (lane == 0)
                s_ir[warp] = rsqrtf(ss * (1.0f / (float)Hn) + EPSf);
        }
        __syncthreads();

        // conv: read all 4 rows (LDS) first, then refill the buffer slot
        float4 vv[CH];
        float  rr[CH];
#pragma unroll
        for (int j = 0; j < CH; j++) {
            vv[j] = bufc[j * H4 + h4];
            rr[j] = s_ir[j];
        }

        // issue chunk c+3 into the buffer just consumed (per-thread LDS above
        // are program-ordered before this thread's cp.async writes)
        if (c + NBUF < NCHUNK) issue(c + NBUF);

#pragma unroll
        for (int j = 0; j < CH; j++) {
            float4 xn;
            xn.x = vv[j].x * rr[j];
            xn.y = vv[j].y * rr[j];
            xn.z = vv[j].z * rr[j];
            xn.w = vv[j].w * rr[j];

            float4 y;
            y.x = fmaf(t0.x, xm3.x, fmaf(t0.y, xm2.x, fmaf(t0.z, xm1.x, fmaf(t0.w, xn.x, bias.x))));
            y.y = fmaf(t1.x, xm3.y, fmaf(t1.y, xm2.y, fmaf(t1.z, xm1.y, fmaf(t1.w, xn.y, bias.y))));
            y.z = fmaf(t2.x, xm3.z, fmaf(t2.y, xm2.z, fmaf(t2.z, xm1.z, fmaf(t2.w, xn.z, bias.z))));
            y.w = fmaf(t3.x, xm3.w, fmaf(t3.y, xm2.w, fmaf(t3.z, xm1.w, fmaf(t3.w, xn.w, bias.w))));

            __stcs(reinterpret_cast<float4*>(ob + (size_t)(s0 + c * CH + j) * Hn) + h4, y);

            xm3 = xm2; xm2 = xm1; xm1 = xn;
        }
    }
}

// ---------------------------------------------------------------------------
// Inputs (metadata order): hidden_states, norm_weight, conv_weight, conv_bias
// ---------------------------------------------------------------------------
extern "C" void kernel_launch(void* const* d_in, const int* in_sizes, int n_in,
                              void* d_out, int out_size) {
    const float* x  = (const float*)d_in[0];
    const float* nw = (const float*)d_in[1];
    const float* cw = (const float*)d_in[2];
    const float* cb = (const float*)d_in[3];
    float* out = (float*)d_out;

    static bool attr_set = false;
    if (!attr_set) {
        cudaFuncSetAttribute(fused_kernel, cudaFuncAttributeMaxDynamicSharedMemorySize,
                             SMEM_BYTES);
        attr_set = true;
    }

    dim3 grid(Sn / RS, Bn);
    fused_kernel<<<grid, 512, SMEM_BYTES>>>(x, nw, cw, cb, out);
}